// round 7
// baseline (speedup 1.0000x reference)
#include <cuda_runtime.h>
#include <cstdint>

typedef unsigned long long u64;

// ---------------- problem constants ----------------
#define TSEQ 16384
#define HID  128
#define GROWS 512   // 4*HID

// ---------------- scratch (device globals; no allocation) ----------------
__device__ float g_pre[(size_t)TSEQ * GROWS];
__device__ float g_h1[(size_t)TSEQ * HID];
__device__ float g_h2[(size_t)TSEQ * HID];

// ---------------- helpers ----------------
__device__ __forceinline__ uint32_t smem_u32(const void* p) {
    return (uint32_t)__cvta_generic_to_shared(p);
}
__device__ __forceinline__ u64 ffma2(u64 a, u64 b, u64 c) {
    u64 d;
    asm("fma.rn.f32x2 %0, %1, %2, %3;" : "=l"(d) : "l"(a), "l"(b), "l"(c));
    return d;
}
__device__ __forceinline__ u64 fadd2(u64 a, u64 b) {
    u64 d;
    asm("add.rn.f32x2 %0, %1, %2;" : "=l"(d) : "l"(a), "l"(b));
    return d;
}
__device__ __forceinline__ float2 unpack2(u64 a) {
    float2 r;
    asm("mov.b64 {%0, %1}, %2;" : "=f"(r.x), "=f"(r.y) : "l"(a));
    return r;
}
__device__ __forceinline__ float fast_sigmoid(float x) {
    return __fdividef(1.f, 1.f + __expf(-x));
}
__device__ __forceinline__ float fast_tanh(float x) {
    return 1.f - __fdividef(2.f, __expf(2.f * x) + 1.f);
}
__device__ __forceinline__ void mbar_wait_cluster(uint32_t addr, unsigned parity) {
    asm volatile(
        "{\n\t"
        ".reg .pred P1;\n\t"
        "WAIT_%=:\n\t"
        "mbarrier.try_wait.parity.acquire.cluster.shared::cta.b64 P1, [%0], %1, 0x989680;\n\t"
        "@P1 bra DONE_%=;\n\t"
        "bra WAIT_%=;\n\t"
        "DONE_%=:\n\t"
        "}"
        :: "r"(addr), "r"(parity) : "memory");
}

// ============================================================================
// LSTM scan: 2-CTA cluster, 256 threads/CTA, all 128 weight cols in regs.
// CTA rank r owns units j in [64r, 64r+64).
// Thread map: lane = 4*(unit%8) + gate -> 4 gates of a unit in adjacent lanes.
//
// SINGLE-ARRIVE PROTOCOL (this round's change):
//   Owners only STORE h remotely (64 distinct-address st.shared::cluster, which
//   pipeline). The per-step remote mbarrier signal is ONE arrive from tid 0,
//   after __syncthreads + fence.acq_rel.cluster. Barrier count = 1.
//   This removes the 64 serialized same-address remote barrier updates that
//   (hypothesis) dominated the 1860-cyc step time in R2/R6.
//
// Per step s:
//   1. local-half matvec on lh[s&3]   (peer h possibly still in flight)
//   2. wait bar_rem[s&3] parity (s>>2)&1   (single peer arrival)
//   3. remote-half matvec on rh[s&3]
//   4. activation + 3 shfls -> owner lane (gate 0)
//   5. owners: c,h update; st.shared::cluster h -> peer rh[(s+1)&3];
//      lh[(s+1)&3] write; stream h to global
//   6. __syncthreads  (publishes lh; hb from all owners to tid 0;
//      certifies all local reads of slot s&3 for ring reuse)
//   7. tid0: fence.acq_rel.cluster; ONE mbarrier.arrive.release.cluster on
//      peer bar[(s+1)&3]
// Ring reuse: CTAs stay in lockstep (each step waits on the other), so a slot
// is rewritten 4 steps after it was read, with syncthreads+arrive chains in
// between — safe.
// ============================================================================
__global__ void __cluster_dims__(2, 1, 1) __launch_bounds__(256, 1)
lstm_scan_kernel(const float* __restrict__ W_hh, int layer)
{
    __shared__ __align__(16) float lh[4][64];   // h of locally-owned units
    __shared__ __align__(16) float rh[4][64];   // h of peer-owned units
    __shared__ __align__(8) u64 bar_rem[4];

    const float* __restrict__ pre = g_pre;
    float* __restrict__ hout = layer ? g_h2 : g_h1;

    const int tid  = threadIdx.x;
    const int lane = tid & 31;
    const int warp = tid >> 5;
    unsigned rank;
    asm("mov.u32 %0, %%cluster_ctarank;" : "=r"(rank));
    const unsigned peer = rank ^ 1u;

    const int gate = lane & 3;                 // 0..3 = i,f,g,o
    const int uc   = warp * 8 + (lane >> 2);   // unit within CTA [0,64)
    const int j    = (int)rank * 64 + uc;      // global hidden unit
    const int row  = gate * HID + j;           // gate row [0,512)

    // ---- weights: local half = cols [64*rank, +64), remote half = other 64
    u64 wl[32], wr_[32];
    {
        const ulonglong2* wsl = reinterpret_cast<const ulonglong2*>(
            W_hh + (size_t)row * HID + 64 * rank);
        const ulonglong2* wsr = reinterpret_cast<const ulonglong2*>(
            W_hh + (size_t)row * HID + 64 * peer);
#pragma unroll
        for (int i = 0; i < 16; i++) {
            ulonglong2 a = wsl[i];
            wl[2 * i] = a.x; wl[2 * i + 1] = a.y;
            ulonglong2 b = wsr[i];
            wr_[2 * i] = b.x; wr_[2 * i + 1] = b.y;
        }
    }

    // ---- init ring slot 0 (h_0 = 0) and barriers (count = 1!)
    if (tid < 64) {
#pragma unroll
        for (int b = 0; b < 4; b++) { lh[b][tid] = 0.f; rh[b][tid] = 0.f; }
    }
    const uint32_t barb = smem_u32(bar_rem);
    if (tid == 0) {
#pragma unroll
        for (int b = 0; b < 4; b++)
            asm volatile("mbarrier.init.shared.b64 [%0], %1;"
                         :: "r"(barb + (unsigned)(b * 8)), "r"(1u));
        // pre-complete slot 0 phase 0 (step-0 input is the zero state)
        asm volatile("mbarrier.arrive.shared::cta.b64 _, [%0];"
                     :: "r"(barb) : "memory");
        asm volatile("fence.mbarrier_init.release.cluster;" ::: "memory");
    }
    __syncthreads();
    asm volatile("barrier.cluster.arrive.aligned;" ::: "memory");
    asm volatile("barrier.cluster.wait.aligned;"   ::: "memory");

    // peer addresses
    uint32_t peer_rh, peer_bar;
    asm("mapa.shared::cluster.u32 %0, %1, %2;"
        : "=r"(peer_rh) : "r"(smem_u32(rh)), "r"(peer));
    asm("mapa.shared::cluster.u32 %0, %1, %2;"
        : "=r"(peer_bar) : "r"(barb), "r"(peer));

    float c = 0.f;                          // cell state (owner lanes, gate 0)
    float pcur = pre[row];                  // pre for step 0
    float pnext = pre[GROWS + row];         // pre for step 1

    for (int s = 0; s < TSEQ; s++) {
        // prefetch pre for s+2 (LDG latency hidden under ~2 steps)
        float pfut = 0.f;
        if (s + 2 < TSEQ) pfut = pre[(size_t)(s + 2) * GROWS + row];

        const int buf = s & 3;
        const unsigned ph = (unsigned)((s >> 2) & 1);

        // ---- 1. local-half matvec (peer data possibly still in flight)
        u64 a0 = 0ull, a1 = 0ull, a2 = 0ull, a3 = 0ull;
        {
            const ulonglong2* hp = reinterpret_cast<const ulonglong2*>(lh[buf]);
#pragma unroll
            for (int i = 0; i < 16; i += 2) {   // 16 x ulonglong2 = 64 floats
                ulonglong2 x = hp[i];
                ulonglong2 y = hp[i + 1];
                a0 = ffma2(wl[2 * i],     x.x, a0);
                a1 = ffma2(wl[2 * i + 1], x.y, a1);
                a2 = ffma2(wl[2 * i + 2], y.x, a2);
                a3 = ffma2(wl[2 * i + 3], y.y, a3);
            }
        }

        // ---- 2. wait for peer's h-half (single arrival)
        mbar_wait_cluster(barb + (unsigned)(buf * 8), ph);

        // ---- 3. remote-half matvec
        {
            const ulonglong2* hp = reinterpret_cast<const ulonglong2*>(rh[buf]);
#pragma unroll
            for (int i = 0; i < 16; i += 2) {
                ulonglong2 x = hp[i];
                ulonglong2 y = hp[i + 1];
                a0 = ffma2(wr_[2 * i],     x.x, a0);
                a1 = ffma2(wr_[2 * i + 1], x.y, a1);
                a2 = ffma2(wr_[2 * i + 2], y.x, a2);
                a3 = ffma2(wr_[2 * i + 3], y.y, a3);
            }
        }
        float2 sm2 = unpack2(fadd2(fadd2(a0, a1), fadd2(a2, a3)));
        float gval = sm2.x + sm2.y + pcur;

        // ---- 4. activation + gather gates to owner lane (gate 0)
        float av = (gate == 2) ? fast_tanh(gval) : fast_sigmoid(gval);
        const unsigned bl = (unsigned)(lane & ~3);
        float fv = __shfl_sync(0xffffffffu, av, bl + 1);
        float gv = __shfl_sync(0xffffffffu, av, bl + 2);
        float ov = __shfl_sync(0xffffffffu, av, bl + 3);

        // ---- 5. owner epilogue: update state, store h (NO per-owner arrive)
        const int nbuf = (s + 1) & 3;
        if (gate == 0) {
            c = fv * c + av * gv;
            float hv = ov * fast_tanh(c);

            // remote data store first: longest flight starts earliest
            const unsigned roff = (unsigned)((nbuf * 64 + uc) * 4);
            asm volatile("st.shared::cluster.f32 [%0], %1;"
                         :: "r"(peer_rh + roff), "f"(hv) : "memory");

            lh[nbuf][uc] = hv;
            hout[(size_t)s * HID + j] = hv;   // off critical path
        }

        // ---- 6. publish lh locally; hb(all owners -> tid 0); certify reads
        __syncthreads();

        // ---- 7. ONE release-arrive to the peer for slot nbuf
        if (tid == 0) {
            asm volatile("fence.acq_rel.cluster;" ::: "memory");
            asm volatile(
                "mbarrier.arrive.release.cluster.shared::cluster.b64 _, [%0];"
                :: "r"(peer_bar + (unsigned)(nbuf * 8)) : "memory");
        }

        pcur = pnext;
        pnext = pfut;
    }

    asm volatile("barrier.cluster.arrive.aligned;" ::: "memory");
    asm volatile("barrier.cluster.wait.aligned;"   ::: "memory");
}

// ============================================================================
// Input projection: g_pre[t, r] = (ba[r] + bb[r]) + sum_k A[t,k] * W[r,k]
// ============================================================================
template <int K>
__global__ void __launch_bounds__(512)
addmm_kernel(const float* __restrict__ Aext, int useH1,
             const float* __restrict__ W,
             const float* __restrict__ ba, const float* __restrict__ bb)
{
    constexpr int BT = 8;
    const float* __restrict__ A = useH1 ? g_h1 : Aext;
    __shared__ float As[BT * K];

    const int t0 = blockIdx.x * BT;
    for (int idx = threadIdx.x; idx < BT * K; idx += 512)
        As[idx] = A[(size_t)t0 * K + idx];
    __syncthreads();

    const int r = threadIdx.x;
    float bias = ba[r] + bb[r];
    float acc[BT];
#pragma unroll
    for (int i = 0; i < BT; i++) acc[i] = bias;

    const float* wr = W + (size_t)r * K;
#pragma unroll 2
    for (int k = 0; k < K; k++) {
        float wv = __ldg(wr + k);
#pragma unroll
        for (int i = 0; i < BT; i++) acc[i] = fmaf(wv, As[i * K + k], acc[i]);
    }
#pragma unroll
    for (int i = 0; i < BT; i++)
        g_pre[(size_t)(t0 + i) * GROWS + r] = acc[i];
}

// ============================================================================
// Final FC: out[t, o] = fc_b[o] + sum_k g_h2[t,k] * fc_W[o,k]   (OUT = 5)
// ============================================================================
__global__ void __launch_bounds__(256)
fc_kernel(const float* __restrict__ fcW, const float* __restrict__ fcb,
          float* __restrict__ out)
{
    __shared__ float Ws[5 * HID];
    __shared__ float bs[5];
    for (int idx = threadIdx.x; idx < 5 * HID; idx += 256) Ws[idx] = fcW[idx];
    if (threadIdx.x < 5) bs[threadIdx.x] = fcb[threadIdx.x];
    __syncthreads();

    const int t = blockIdx.x * 256 + threadIdx.x;
    float acc[5];
#pragma unroll
    for (int o = 0; o < 5; o++) acc[o] = bs[o];

    const float4* hp = reinterpret_cast<const float4*>(&g_h2[(size_t)t * HID]);
#pragma unroll 4
    for (int k4 = 0; k4 < HID / 4; k4++) {
        float4 h = hp[k4];
#pragma unroll
        for (int o = 0; o < 5; o++) {
            acc[o] = fmaf(h.x, Ws[o * HID + 4 * k4 + 0], acc[o]);
            acc[o] = fmaf(h.y, Ws[o * HID + 4 * k4 + 1], acc[o]);
            acc[o] = fmaf(h.z, Ws[o * HID + 4 * k4 + 2], acc[o]);
            acc[o] = fmaf(h.w, Ws[o * HID + 4 * k4 + 3], acc[o]);
        }
    }
#pragma unroll
    for (int o = 0; o < 5; o++) out[(size_t)t * 5 + o] = acc[o];
}

// ============================================================================
// kernel_launch: pre1 GEMM -> scan L1 -> pre2 GEMM -> scan L2 -> FC
// ============================================================================
extern "C" void kernel_launch(void* const* d_in, const int* in_sizes, int n_in,
                              void* d_out, int out_size)
{
    (void)in_sizes; (void)n_in; (void)out_size;

    const float* x     = (const float*)d_in[0];
    const float* W_ih1 = (const float*)d_in[1];
    const float* W_hh1 = (const float*)d_in[2];
    const float* b_ih1 = (const float*)d_in[3];
    const float* b_hh1 = (const float*)d_in[4];
    const float* W_ih2 = (const float*)d_in[5];
    const float* W_hh2 = (const float*)d_in[6];
    const float* b_ih2 = (const float*)d_in[7];
    const float* b_hh2 = (const float*)d_in[8];
    const float* fc_W  = (const float*)d_in[9];
    const float* fc_b  = (const float*)d_in[10];
    float* out = (float*)d_out;

    addmm_kernel<50><<<TSEQ / 8, 512>>>(x, 0, W_ih1, b_ih1, b_hh1);
    lstm_scan_kernel<<<2, 256>>>(W_hh1, 0);
    addmm_kernel<128><<<TSEQ / 8, 512>>>(nullptr, 1, W_ih2, b_ih2, b_hh2);
    lstm_scan_kernel<<<2, 256>>>(W_hh2, 1);
    fc_kernel<<<TSEQ / 256, 256>>>(fc_W, fc_b, out);
}

// round 8
// speedup vs baseline: 1.7586x; 1.7586x over previous
#include <cuda_runtime.h>
#include <cstdint>

typedef unsigned long long u64;

// ---------------- problem constants ----------------
#define TSEQ 16384
#define HID  128
#define GROWS 512   // 4*HID

// ---------------- scratch (device globals; no allocation) ----------------
__device__ float g_pre[(size_t)TSEQ * GROWS];
__device__ float g_h1[(size_t)TSEQ * HID];
__device__ float g_h2[(size_t)TSEQ * HID];

// ---------------- helpers ----------------
__device__ __forceinline__ uint32_t smem_u32(const void* p) {
    return (uint32_t)__cvta_generic_to_shared(p);
}
__device__ __forceinline__ u64 ffma2(u64 a, u64 b, u64 c) {
    u64 d;
    asm("fma.rn.f32x2 %0, %1, %2, %3;" : "=l"(d) : "l"(a), "l"(b), "l"(c));
    return d;
}
__device__ __forceinline__ u64 fadd2(u64 a, u64 b) {
    u64 d;
    asm("add.rn.f32x2 %0, %1, %2;" : "=l"(d) : "l"(a), "l"(b));
    return d;
}
__device__ __forceinline__ float2 unpack2(u64 a) {
    float2 r;
    asm("mov.b64 {%0, %1}, %2;" : "=f"(r.x), "=f"(r.y) : "l"(a));
    return r;
}
__device__ __forceinline__ float fast_sigmoid(float x) {
    return __fdividef(1.f, 1.f + __expf(-x));
}
__device__ __forceinline__ float fast_tanh(float x) {
    return 1.f - __fdividef(2.f, __expf(2.f * x) + 1.f);
}
// CTA-scope acquire wait (cheap; data visibility via tx-completion contract)
__device__ __forceinline__ void mbar_wait_cta(uint32_t addr, unsigned parity) {
    asm volatile(
        "{\n\t"
        ".reg .pred P1;\n\t"
        "WAIT_%=:\n\t"
        "mbarrier.try_wait.parity.acquire.cta.shared::cta.b64 P1, [%0], %1, 0x989680;\n\t"
        "@P1 bra DONE_%=;\n\t"
        "bra WAIT_%=;\n\t"
        "DONE_%=:\n\t"
        "}"
        :: "r"(addr), "r"(parity) : "memory");
}

// ============================================================================
// LSTM scan: 2-CTA cluster, 256 threads/CTA, all 128 weight cols in regs.
// CTA rank r owns units j in [64r, 64r+64).
// Thread map: lane = 4*(unit%8) + gate -> 4 gates of a unit in adjacent lanes.
//
// ST.ASYNC + TX-BARRIER PROTOCOL (this round's change):
//   Producers push h into the peer's rh ring via
//     st.async.shared::cluster.mbarrier::complete_tx::bytes (4B tx each).
//   Consumer barrier slots: count=1; tid0 re-arms a slot right after
//   consuming it with mbarrier.arrive.expect_tx(256B). Phase completes when
//   all 64 stores (256B) have LANDED -> data visibility guaranteed by the
//   barrier contract (TMA-style). Wait is try_wait.parity.acquire.CTA —
//   no cluster-scope acquire, no release-arrive, no cluster fence in loop.
//
// Per step s (buf = s&3, parity (s>>2)&1):
//   1. local-half matvec on lh[buf]
//   2. wait bar[buf] (cta-acquire)      3. tid0 re-arms bar[buf] (+256B)
//   4. remote-half matvec on rh[buf]
//   5. activation + 3 shfls -> owner lane (gate 0)
//   6. owners: c,h update; st.async h -> peer rh[(s+1)&3]/bar[(s+1)&3];
//      lh[(s+1)&3] write; stream h to global
//   7. __syncthreads (publish lh; certify ring reads; order re-arm vs
//      future local stores)
// Re-arm safety: re-arm @ step s precedes (program+sync order) my stores
// @ step s+2, which gate the peer's wait @ s+3, which gates the peer's
// stores @ s+3 — the earliest traffic into the re-armed phase. The barrier
// itself transitions phase atomically at completion, so expects always land
// in the not-yet-filled phase.
// ============================================================================
__global__ void __cluster_dims__(2, 1, 1) __launch_bounds__(256, 1)
lstm_scan_kernel(const float* __restrict__ W_hh, int layer)
{
    __shared__ __align__(16) float lh[4][64];   // h of locally-owned units
    __shared__ __align__(16) float rh[4][64];   // h of peer-owned units (pushed)
    __shared__ __align__(8) u64 bar_rem[4];

    const float* __restrict__ pre = g_pre;
    float* __restrict__ hout = layer ? g_h2 : g_h1;

    const int tid  = threadIdx.x;
    const int lane = tid & 31;
    const int warp = tid >> 5;
    unsigned rank;
    asm("mov.u32 %0, %%cluster_ctarank;" : "=r"(rank));
    const unsigned peer = rank ^ 1u;

    const int gate = lane & 3;                 // 0..3 = i,f,g,o
    const int uc   = warp * 8 + (lane >> 2);   // unit within CTA [0,64)
    const int j    = (int)rank * 64 + uc;      // global hidden unit
    const int row  = gate * HID + j;           // gate row [0,512)

    // ---- weights: local half = cols [64*rank, +64), remote half = other 64
    u64 wl[32], wr_[32];
    {
        const ulonglong2* wsl = reinterpret_cast<const ulonglong2*>(
            W_hh + (size_t)row * HID + 64 * rank);
        const ulonglong2* wsr = reinterpret_cast<const ulonglong2*>(
            W_hh + (size_t)row * HID + 64 * peer);
#pragma unroll
        for (int i = 0; i < 16; i++) {
            ulonglong2 a = wsl[i];
            wl[2 * i] = a.x; wl[2 * i + 1] = a.y;
            ulonglong2 b = wsr[i];
            wr_[2 * i] = b.x; wr_[2 * i + 1] = b.y;
        }
    }

    // ---- init ring slot 0 (h_0 = 0) and tx-barriers (count = 1)
    if (tid < 64) {
#pragma unroll
        for (int b = 0; b < 4; b++) { lh[b][tid] = 0.f; rh[b][tid] = 0.f; }
    }
    const uint32_t barb = smem_u32(bar_rem);
    if (tid == 0) {
#pragma unroll
        for (int b = 0; b < 4; b++)
            asm volatile("mbarrier.init.shared.b64 [%0], %1;"
                         :: "r"(barb + (unsigned)(b * 8)), "r"(1u));
        // slot 0: phase 0 completes immediately (step-0 input is zero state)
        asm volatile("mbarrier.arrive.shared::cta.b64 _, [%0];"
                     :: "r"(barb) : "memory");
        // slots 1..3: armed for the peer's pushes of h_1..h_3 (256B each)
#pragma unroll
        for (int b = 1; b < 4; b++)
            asm volatile("mbarrier.arrive.expect_tx.shared.b64 _, [%0], %1;"
                         :: "r"(barb + (unsigned)(b * 8)), "r"(256u) : "memory");
        asm volatile("fence.mbarrier_init.release.cluster;" ::: "memory");
    }
    __syncthreads();
    asm volatile("barrier.cluster.arrive.aligned;" ::: "memory");
    asm volatile("barrier.cluster.wait.aligned;"   ::: "memory");

    // peer addresses
    uint32_t peer_rh, peer_bar;
    asm("mapa.shared::cluster.u32 %0, %1, %2;"
        : "=r"(peer_rh) : "r"(smem_u32(rh)), "r"(peer));
    asm("mapa.shared::cluster.u32 %0, %1, %2;"
        : "=r"(peer_bar) : "r"(barb), "r"(peer));

    float c = 0.f;                          // cell state (owner lanes, gate 0)
    float pcur = pre[row];                  // pre for step 0
    float pnext = pre[GROWS + row];         // pre for step 1

    for (int s = 0; s < TSEQ; s++) {
        // prefetch pre for s+2 (LDG latency hidden under ~2 steps)
        float pfut = 0.f;
        if (s + 2 < TSEQ) pfut = pre[(size_t)(s + 2) * GROWS + row];

        const int buf = s & 3;
        const unsigned ph = (unsigned)((s >> 2) & 1);

        // ---- 1. local-half matvec (peer data possibly still in flight)
        u64 a0 = 0ull, a1 = 0ull, a2 = 0ull, a3 = 0ull;
        {
            const ulonglong2* hp = reinterpret_cast<const ulonglong2*>(lh[buf]);
#pragma unroll
            for (int i = 0; i < 16; i += 2) {   // 16 x ulonglong2 = 64 floats
                ulonglong2 x = hp[i];
                ulonglong2 y = hp[i + 1];
                a0 = ffma2(wl[2 * i],     x.x, a0);
                a1 = ffma2(wl[2 * i + 1], x.y, a1);
                a2 = ffma2(wl[2 * i + 2], y.x, a2);
                a3 = ffma2(wl[2 * i + 3], y.y, a3);
            }
        }

        // ---- 2. wait for peer's h-half (tx completion, cta-scope acquire)
        mbar_wait_cta(barb + (unsigned)(buf * 8), ph);

        // ---- 3. re-arm this slot for its next fill (peer's step s+3)
        if (tid == 0)
            asm volatile("mbarrier.arrive.expect_tx.shared.b64 _, [%0], %1;"
                         :: "r"(barb + (unsigned)(buf * 8)), "r"(256u) : "memory");

        // ---- 4. remote-half matvec
        {
            const ulonglong2* hp = reinterpret_cast<const ulonglong2*>(rh[buf]);
#pragma unroll
            for (int i = 0; i < 16; i += 2) {
                ulonglong2 x = hp[i];
                ulonglong2 y = hp[i + 1];
                a0 = ffma2(wr_[2 * i],     x.x, a0);
                a1 = ffma2(wr_[2 * i + 1], x.y, a1);
                a2 = ffma2(wr_[2 * i + 2], y.x, a2);
                a3 = ffma2(wr_[2 * i + 3], y.y, a3);
            }
        }
        float2 sm2 = unpack2(fadd2(fadd2(a0, a1), fadd2(a2, a3)));
        float gval = sm2.x + sm2.y + pcur;

        // ---- 5. activation + gather gates to owner lane (gate 0)
        float av = (gate == 2) ? fast_tanh(gval) : fast_sigmoid(gval);
        const unsigned bl = (unsigned)(lane & ~3);
        float fv = __shfl_sync(0xffffffffu, av, bl + 1);
        float gv = __shfl_sync(0xffffffffu, av, bl + 2);
        float ov = __shfl_sync(0xffffffffu, av, bl + 3);

        // ---- 6. owner epilogue: update state, push h via st.async
        const int nbuf = (s + 1) & 3;
        if (gate == 0) {
            c = fv * c + av * gv;
            float hv = ov * fast_tanh(c);

            // async push: data + 4B tx completion on the peer's barrier
            const unsigned roff = (unsigned)((nbuf * 64 + uc) * 4);
            asm volatile(
                "st.async.shared::cluster.mbarrier::complete_tx::bytes.b32 "
                "[%0], %1, [%2];"
                :: "r"(peer_rh + roff), "r"(__float_as_uint(hv)),
                   "r"(peer_bar + (unsigned)(nbuf * 8)) : "memory");

            lh[nbuf][uc] = hv;
            hout[(size_t)s * HID + j] = hv;   // off critical path
        }

        // ---- 7. publish lh; certify ring reads; order re-arm vs next stores
        __syncthreads();

        pcur = pnext;
        pnext = pfut;
    }

    asm volatile("barrier.cluster.arrive.aligned;" ::: "memory");
    asm volatile("barrier.cluster.wait.aligned;"   ::: "memory");
}

// ============================================================================
// Input projection: g_pre[t, r] = (ba[r] + bb[r]) + sum_k A[t,k] * W[r,k]
// ============================================================================
template <int K>
__global__ void __launch_bounds__(512)
addmm_kernel(const float* __restrict__ Aext, int useH1,
             const float* __restrict__ W,
             const float* __restrict__ ba, const float* __restrict__ bb)
{
    constexpr int BT = 8;
    const float* __restrict__ A = useH1 ? g_h1 : Aext;
    __shared__ float As[BT * K];

    const int t0 = blockIdx.x * BT;
    for (int idx = threadIdx.x; idx < BT * K; idx += 512)
        As[idx] = A[(size_t)t0 * K + idx];
    __syncthreads();

    const int r = threadIdx.x;
    float bias = ba[r] + bb[r];
    float acc[BT];
#pragma unroll
    for (int i = 0; i < BT; i++) acc[i] = bias;

    const float* wr = W + (size_t)r * K;
#pragma unroll 2
    for (int k = 0; k < K; k++) {
        float wv = __ldg(wr + k);
#pragma unroll
        for (int i = 0; i < BT; i++) acc[i] = fmaf(wv, As[i * K + k], acc[i]);
    }
#pragma unroll
    for (int i = 0; i < BT; i++)
        g_pre[(size_t)(t0 + i) * GROWS + r] = acc[i];
}

// ============================================================================
// Final FC: out[t, o] = fc_b[o] + sum_k g_h2[t,k] * fc_W[o,k]   (OUT = 5)
// ============================================================================
__global__ void __launch_bounds__(256)
fc_kernel(const float* __restrict__ fcW, const float* __restrict__ fcb,
          float* __restrict__ out)
{
    __shared__ float Ws[5 * HID];
    __shared__ float bs[5];
    for (int idx = threadIdx.x; idx < 5 * HID; idx += 256) Ws[idx] = fcW[idx];
    if (threadIdx.x < 5) bs[threadIdx.x] = fcb[threadIdx.x];
    __syncthreads();

    const int t = blockIdx.x * 256 + threadIdx.x;
    float acc[5];
#pragma unroll
    for (int o = 0; o < 5; o++) acc[o] = bs[o];

    const float4* hp = reinterpret_cast<const float4*>(&g_h2[(size_t)t * HID]);
#pragma unroll 4
    for (int k4 = 0; k4 < HID / 4; k4++) {
        float4 h = hp[k4];
#pragma unroll
        for (int o = 0; o < 5; o++) {
            acc[o] = fmaf(h.x, Ws[o * HID + 4 * k4 + 0], acc[o]);
            acc[o] = fmaf(h.y, Ws[o * HID + 4 * k4 + 1], acc[o]);
            acc[o] = fmaf(h.z, Ws[o * HID + 4 * k4 + 2], acc[o]);
            acc[o] = fmaf(h.w, Ws[o * HID + 4 * k4 + 3], acc[o]);
        }
    }
#pragma unroll
    for (int o = 0; o < 5; o++) out[(size_t)t * 5 + o] = acc[o];
}

// ============================================================================
// kernel_launch: pre1 GEMM -> scan L1 -> pre2 GEMM -> scan L2 -> FC
// ============================================================================
extern "C" void kernel_launch(void* const* d_in, const int* in_sizes, int n_in,
                              void* d_out, int out_size)
{
    (void)in_sizes; (void)n_in; (void)out_size;

    const float* x     = (const float*)d_in[0];
    const float* W_ih1 = (const float*)d_in[1];
    const float* W_hh1 = (const float*)d_in[2];
    const float* b_ih1 = (const float*)d_in[3];
    const float* b_hh1 = (const float*)d_in[4];
    const float* W_ih2 = (const float*)d_in[5];
    const float* W_hh2 = (const float*)d_in[6];
    const float* b_ih2 = (const float*)d_in[7];
    const float* b_hh2 = (const float*)d_in[8];
    const float* fc_W  = (const float*)d_in[9];
    const float* fc_b  = (const float*)d_in[10];
    float* out = (float*)d_out;

    addmm_kernel<50><<<TSEQ / 8, 512>>>(x, 0, W_ih1, b_ih1, b_hh1);
    lstm_scan_kernel<<<2, 256>>>(W_hh1, 0);
    addmm_kernel<128><<<TSEQ / 8, 512>>>(nullptr, 1, W_ih2, b_ih2, b_hh2);
    lstm_scan_kernel<<<2, 256>>>(W_hh2, 1);
    fc_kernel<<<TSEQ / 256, 256>>>(fc_W, fc_b, out);
}

// round 9
// speedup vs baseline: 1.7999x; 1.0235x over previous
#include <cuda_runtime.h>
#include <cstdint>

typedef unsigned long long u64;

// ---------------- problem constants ----------------
#define TSEQ 16384
#define HID  128
#define GROWS 512   // 4*HID
#define CHUNK 256
#define NCHUNK (TSEQ / CHUNK)
#define NGEMM 4

// ---------------- scratch (device globals; no allocation) ----------------
__device__ float g_pre [(size_t)TSEQ * GROWS];  // layer-1 gate inputs
__device__ float g_pre2[(size_t)TSEQ * GROWS];  // layer-2 gate inputs (streamed)
__device__ float g_h1[(size_t)TSEQ * HID];
__device__ float g_h2[(size_t)TSEQ * HID];
__device__ int   g_flag1[NCHUNK];               // L1 chunk-k h1 complete
__device__ int   g_done [NCHUNK];               // pre2 chunk-k complete (count to NGEMM)

// ---------------- helpers ----------------
__device__ __forceinline__ uint32_t smem_u32(const void* p) {
    return (uint32_t)__cvta_generic_to_shared(p);
}
__device__ __forceinline__ u64 ffma2(u64 a, u64 b, u64 c) {
    u64 d;
    asm("fma.rn.f32x2 %0, %1, %2, %3;" : "=l"(d) : "l"(a), "l"(b), "l"(c));
    return d;
}
__device__ __forceinline__ u64 fadd2(u64 a, u64 b) {
    u64 d;
    asm("add.rn.f32x2 %0, %1, %2;" : "=l"(d) : "l"(a), "l"(b));
    return d;
}
__device__ __forceinline__ float2 unpack2(u64 a) {
    float2 r;
    asm("mov.b64 {%0, %1}, %2;" : "=f"(r.x), "=f"(r.y) : "l"(a));
    return r;
}
__device__ __forceinline__ float fast_sigmoid(float x) {
    return __fdividef(1.f, 1.f + __expf(-x));
}
__device__ __forceinline__ float fast_tanh(float x) {
    return 1.f - __fdividef(2.f, __expf(2.f * x) + 1.f);
}
__device__ __forceinline__ void mbar_wait_cta(uint32_t addr, unsigned parity) {
    asm volatile(
        "{\n\t"
        ".reg .pred P1;\n\t"
        "WAIT_%=:\n\t"
        "mbarrier.try_wait.parity.acquire.cta.shared::cta.b64 P1, [%0], %1, 0x989680;\n\t"
        "@P1 bra DONE_%=;\n\t"
        "bra WAIT_%=;\n\t"
        "DONE_%=:\n\t"
        "}"
        :: "r"(addr), "r"(parity) : "memory");
}
__device__ __forceinline__ void st_release_gpu(int* p, int v) {
    asm volatile("st.release.gpu.global.s32 [%0], %1;" :: "l"(p), "r"(v) : "memory");
}
__device__ __forceinline__ int ld_acquire_gpu(const int* p) {
    int v;
    asm volatile("ld.acquire.gpu.global.s32 %0, [%1];" : "=r"(v) : "l"(p) : "memory");
    return v;
}

// ============================================================================
// Fused pipeline kernel. grid = 8, cluster_dims = 2, 256 thr/CTA.
//   cluster 0 (CTA 0,1): layer-1 LSTM scan (R8 st.async protocol, unchanged)
//   cluster 1 (CTA 2,3): layer-2 LSTM scan, chunk-gated on g_done
//   cluster 2,3 (CTA 4..7): pre2 GEMM workers, chunk-gated on g_flag1
// Wait graph is acyclic: L1 -> GEMM -> L2. Full-size buffers => no backpressure.
// ============================================================================
__global__ void __cluster_dims__(2, 1, 1) __launch_bounds__(256, 1)
fused_lstm_kernel(const float* __restrict__ W_hh1,
                  const float* __restrict__ W_hh2,
                  const float* __restrict__ W_ih2,
                  const float* __restrict__ b_ih2,
                  const float* __restrict__ b_hh2)
{
    __shared__ __align__(16) float lh[4][64];
    __shared__ __align__(16) float rh[4][64];
    __shared__ __align__(8) u64 bar_rem[4];
    __shared__ __align__(16) float As[8 * HID];   // GEMM h1 staging

    const int tid = threadIdx.x;
    const int cid = blockIdx.x >> 1;              // cluster id 0..3

    // ========================== GEMM worker path ==========================
    if (cid >= 2) {
        const int w = blockIdx.x - 4;             // 0..NGEMM-1
        const float bias0 = b_ih2[tid] + b_hh2[tid];
        const float bias1 = b_ih2[tid + 256] + b_hh2[tid + 256];
        const float* wr0 = W_ih2 + (size_t)tid * HID;
        const float* wr1 = W_ih2 + (size_t)(tid + 256) * HID;

        for (int k = 0; k < NCHUNK; k++) {
            if (tid == 0) while (ld_acquire_gpu(&g_flag1[k]) == 0) {}
            __syncthreads();

            const int tbase = k * CHUNK + w * (CHUNK / NGEMM);
            for (int b = 0; b < (CHUNK / NGEMM) / 8; b++) {
                const int t0 = tbase + b * 8;
                for (int idx = tid; idx < 8 * HID; idx += 256)
                    As[idx] = g_h1[(size_t)t0 * HID + idx];
                __syncthreads();

                float acc0[8], acc1[8];
#pragma unroll
                for (int i = 0; i < 8; i++) { acc0[i] = bias0; acc1[i] = bias1; }
#pragma unroll 4
                for (int kk = 0; kk < HID; kk++) {
                    float w0 = __ldg(wr0 + kk);
                    float w1 = __ldg(wr1 + kk);
#pragma unroll
                    for (int i = 0; i < 8; i++) {
                        float hvv = As[i * HID + kk];
                        acc0[i] = fmaf(w0, hvv, acc0[i]);
                        acc1[i] = fmaf(w1, hvv, acc1[i]);
                    }
                }
#pragma unroll
                for (int i = 0; i < 8; i++) {
                    g_pre2[(size_t)(t0 + i) * GROWS + tid]       = acc0[i];
                    g_pre2[(size_t)(t0 + i) * GROWS + tid + 256] = acc1[i];
                }
                __syncthreads();
            }
            __syncthreads();
            if (tid == 0) { __threadfence(); atomicAdd(&g_done[k], 1); }
        }
        return;
    }

    // ============================ scan path ================================
    const int layer = cid;                         // 0 or 1
    const float* __restrict__ pre = layer ? g_pre2 : g_pre;
    float* __restrict__ hout = layer ? g_h2 : g_h1;
    const float* __restrict__ W_hh = layer ? W_hh2 : W_hh1;

    const int lane = tid & 31;
    const int warp = tid >> 5;
    unsigned rank;
    asm("mov.u32 %0, %%cluster_ctarank;" : "=r"(rank));
    const unsigned peer = rank ^ 1u;

    const int gate = lane & 3;                 // 0..3 = i,f,g,o
    const int uc   = warp * 8 + (lane >> 2);   // unit within CTA [0,64)
    const int j    = (int)rank * 64 + uc;      // global hidden unit
    const int row  = gate * HID + j;           // gate row [0,512)

    // ---- weights: local half = cols [64*rank, +64), remote half = other 64
    u64 wl[32], wr_[32];
    {
        const ulonglong2* wsl = reinterpret_cast<const ulonglong2*>(
            W_hh + (size_t)row * HID + 64 * rank);
        const ulonglong2* wsr = reinterpret_cast<const ulonglong2*>(
            W_hh + (size_t)row * HID + 64 * peer);
#pragma unroll
        for (int i = 0; i < 16; i++) {
            ulonglong2 a = wsl[i];
            wl[2 * i] = a.x; wl[2 * i + 1] = a.y;
            ulonglong2 b = wsr[i];
            wr_[2 * i] = b.x; wr_[2 * i + 1] = b.y;
        }
    }

    // ---- init ring slot 0 (h_0 = 0) and tx-barriers (count = 1)
    if (tid < 64) {
#pragma unroll
        for (int b = 0; b < 4; b++) { lh[b][tid] = 0.f; rh[b][tid] = 0.f; }
    }
    const uint32_t barb = smem_u32(bar_rem);
    if (tid == 0) {
#pragma unroll
        for (int b = 0; b < 4; b++)
            asm volatile("mbarrier.init.shared.b64 [%0], %1;"
                         :: "r"(barb + (unsigned)(b * 8)), "r"(1u));
        asm volatile("mbarrier.arrive.shared::cta.b64 _, [%0];"
                     :: "r"(barb) : "memory");
#pragma unroll
        for (int b = 1; b < 4; b++)
            asm volatile("mbarrier.arrive.expect_tx.shared.b64 _, [%0], %1;"
                         :: "r"(barb + (unsigned)(b * 8)), "r"(256u) : "memory");
        asm volatile("fence.mbarrier_init.release.cluster;" ::: "memory");
    }
    __syncthreads();
    asm volatile("barrier.cluster.arrive.aligned;" ::: "memory");
    asm volatile("barrier.cluster.wait.aligned;"   ::: "memory");

    uint32_t peer_rh, peer_bar;
    asm("mapa.shared::cluster.u32 %0, %1, %2;"
        : "=r"(peer_rh) : "r"(smem_u32(rh)), "r"(peer));
    asm("mapa.shared::cluster.u32 %0, %1, %2;"
        : "=r"(peer_bar) : "r"(barb), "r"(peer));

    float c = 0.f;                          // cell state (owner lanes, gate 0)

    for (int k = 0; k < NCHUNK; k++) {
        // L2 gates on pre2-chunk completion (acquire); L1 runs free
        if (layer == 1) {
            if (tid == 0) while (ld_acquire_gpu(&g_done[k]) < NGEMM) {}
            __syncthreads();
        }

        const int s0 = k * CHUNK;
        // chunk-local gate-input staging (never reads past the acquired chunk)
        float pcur  = pre[(size_t)s0 * GROWS + row];
        float pnext = pre[(size_t)(s0 + 1) * GROWS + row];

        for (int si = 0; si < CHUNK; si++) {
            const int s = s0 + si;
            float pfut = 0.f;
            if (si + 2 < CHUNK) pfut = pre[(size_t)(s + 2) * GROWS + row];

            const int buf = s & 3;
            const unsigned ph = (unsigned)((s >> 2) & 1);

            // ---- 1. local-half matvec
            u64 a0 = 0ull, a1 = 0ull, a2 = 0ull, a3 = 0ull;
            {
                const ulonglong2* hp = reinterpret_cast<const ulonglong2*>(lh[buf]);
#pragma unroll
                for (int i = 0; i < 16; i += 2) {
                    ulonglong2 x = hp[i];
                    ulonglong2 y = hp[i + 1];
                    a0 = ffma2(wl[2 * i],     x.x, a0);
                    a1 = ffma2(wl[2 * i + 1], x.y, a1);
                    a2 = ffma2(wl[2 * i + 2], y.x, a2);
                    a3 = ffma2(wl[2 * i + 3], y.y, a3);
                }
            }

            // ---- 2. wait peer tx (cta-scope acquire)
            mbar_wait_cta(barb + (unsigned)(buf * 8), ph);

            // ---- 3. re-arm slot for its next fill
            if (tid == 0)
                asm volatile("mbarrier.arrive.expect_tx.shared.b64 _, [%0], %1;"
                             :: "r"(barb + (unsigned)(buf * 8)), "r"(256u) : "memory");

            // ---- 4. remote-half matvec
            {
                const ulonglong2* hp = reinterpret_cast<const ulonglong2*>(rh[buf]);
#pragma unroll
                for (int i = 0; i < 16; i += 2) {
                    ulonglong2 x = hp[i];
                    ulonglong2 y = hp[i + 1];
                    a0 = ffma2(wr_[2 * i],     x.x, a0);
                    a1 = ffma2(wr_[2 * i + 1], x.y, a1);
                    a2 = ffma2(wr_[2 * i + 2], y.x, a2);
                    a3 = ffma2(wr_[2 * i + 3], y.y, a3);
                }
            }
            float2 sm2 = unpack2(fadd2(fadd2(a0, a1), fadd2(a2, a3)));
            float gval = sm2.x + sm2.y + pcur;

            // ---- 5. activation + gather to owner lane
            float av = (gate == 2) ? fast_tanh(gval) : fast_sigmoid(gval);
            const unsigned bl = (unsigned)(lane & ~3);
            float fv = __shfl_sync(0xffffffffu, av, bl + 1);
            float gv = __shfl_sync(0xffffffffu, av, bl + 2);
            float ov = __shfl_sync(0xffffffffu, av, bl + 3);

            // ---- 6. owner epilogue
            const int nbuf = (s + 1) & 3;
            if (gate == 0) {
                c = fv * c + av * gv;
                float hv = ov * fast_tanh(c);

                const unsigned roff = (unsigned)((nbuf * 64 + uc) * 4);
                asm volatile(
                    "st.async.shared::cluster.mbarrier::complete_tx::bytes.b32 "
                    "[%0], %1, [%2];"
                    :: "r"(peer_rh + roff), "r"(__float_as_uint(hv)),
                       "r"(peer_bar + (unsigned)(nbuf * 8)) : "memory");

                lh[nbuf][uc] = hv;
                hout[(size_t)s * HID + j] = hv;
            }

            // ---- 7. publish lh; certify ring reads
            __syncthreads();

            pcur = pnext;
            pnext = pfut;
        }

        // L1 publishes "h1 chunk k complete" (all owners' STGs precede the bar)
        if (layer == 0) {
            if (tid == 0) { __threadfence(); st_release_gpu(&g_flag1[k], 1); }
        }
    }

    asm volatile("barrier.cluster.arrive.aligned;" ::: "memory");
    asm volatile("barrier.cluster.wait.aligned;"   ::: "memory");
}

// ============================================================================
// pre1 = x @ W_ih1^T + (b_ih1 + b_hh1); block 0 also zeroes the pipe flags.
// ============================================================================
__global__ void __launch_bounds__(512)
pre1_kernel(const float* __restrict__ x, const float* __restrict__ W,
            const float* __restrict__ ba, const float* __restrict__ bb)
{
    constexpr int K = 50, BT = 8;
    __shared__ float Axs[BT * K];

    if (blockIdx.x == 0 && threadIdx.x < NCHUNK) {
        g_flag1[threadIdx.x] = 0;
        g_done[threadIdx.x]  = 0;
    }

    const int t0 = blockIdx.x * BT;
    for (int idx = threadIdx.x; idx < BT * K; idx += 512)
        Axs[idx] = x[(size_t)t0 * K + idx];
    __syncthreads();

    const int r = threadIdx.x;
    float bias = ba[r] + bb[r];
    float acc[BT];
#pragma unroll
    for (int i = 0; i < BT; i++) acc[i] = bias;

    const float* wr = W + (size_t)r * K;
#pragma unroll 2
    for (int k = 0; k < K; k++) {
        float wv = __ldg(wr + k);
#pragma unroll
        for (int i = 0; i < BT; i++) acc[i] = fmaf(wv, Axs[i * K + k], acc[i]);
    }
#pragma unroll
    for (int i = 0; i < BT; i++)
        g_pre[(size_t)(t0 + i) * GROWS + r] = acc[i];
}

// ============================================================================
// Final FC: out[t, o] = fc_b[o] + sum_k g_h2[t,k] * fc_W[o,k]   (OUT = 5)
// ============================================================================
__global__ void __launch_bounds__(256)
fc_kernel(const float* __restrict__ fcW, const float* __restrict__ fcb,
          float* __restrict__ out)
{
    __shared__ float Ws[5 * HID];
    __shared__ float bs[5];
    for (int idx = threadIdx.x; idx < 5 * HID; idx += 256) Ws[idx] = fcW[idx];
    if (threadIdx.x < 5) bs[threadIdx.x] = fcb[threadIdx.x];
    __syncthreads();

    const int t = blockIdx.x * 256 + threadIdx.x;
    float acc[5];
#pragma unroll
    for (int o = 0; o < 5; o++) acc[o] = bs[o];

    const float4* hp = reinterpret_cast<const float4*>(&g_h2[(size_t)t * HID]);
#pragma unroll 4
    for (int k4 = 0; k4 < HID / 4; k4++) {
        float4 h = hp[k4];
#pragma unroll
        for (int o = 0; o < 5; o++) {
            acc[o] = fmaf(h.x, Ws[o * HID + 4 * k4 + 0], acc[o]);
            acc[o] = fmaf(h.y, Ws[o * HID + 4 * k4 + 1], acc[o]);
            acc[o] = fmaf(h.z, Ws[o * HID + 4 * k4 + 2], acc[o]);
            acc[o] = fmaf(h.w, Ws[o * HID + 4 * k4 + 3], acc[o]);
        }
    }
#pragma unroll
    for (int o = 0; o < 5; o++) out[(size_t)t * 5 + o] = acc[o];
}

// ============================================================================
// kernel_launch: pre1 (+flag reset) -> fused pipeline (L1 | GEMM | L2) -> FC
// ============================================================================
extern "C" void kernel_launch(void* const* d_in, const int* in_sizes, int n_in,
                              void* d_out, int out_size)
{
    (void)in_sizes; (void)n_in; (void)out_size;

    const float* x     = (const float*)d_in[0];
    const float* W_ih1 = (const float*)d_in[1];
    const float* W_hh1 = (const float*)d_in[2];
    const float* b_ih1 = (const float*)d_in[3];
    const float* b_hh1 = (const float*)d_in[4];
    const float* W_ih2 = (const float*)d_in[5];
    const float* W_hh2 = (const float*)d_in[6];
    const float* b_ih2 = (const float*)d_in[7];
    const float* b_hh2 = (const float*)d_in[8];
    const float* fc_W  = (const float*)d_in[9];
    const float* fc_b  = (const float*)d_in[10];
    float* out = (float*)d_out;

    pre1_kernel<<<TSEQ / 8, 512>>>(x, W_ih1, b_ih1, b_hh1);
    fused_lstm_kernel<<<8, 256>>>(W_hh1, W_hh2, W_ih2, b_ih2, b_hh2);
    fc_kernel<<<TSEQ / 256, 256>>>(fc_W, fc_b, out);
}

// round 10
// speedup vs baseline: 3.4640x; 1.9246x over previous
#include <cuda_runtime.h>
#include <cstdint>

typedef unsigned long long u64;

// ---------------- problem constants ----------------
#define TSEQ 16384
#define HID  128
#define GROWS 512   // 4*HID
#define CHUNK 256
#define NCHUNK (TSEQ / CHUNK)
#define NGEMM 32

// ---------------- scratch (device globals; no allocation) ----------------
__device__ float g_pre [(size_t)TSEQ * GROWS];  // layer-1 gate inputs
__device__ float g_pre2[(size_t)TSEQ * GROWS];  // layer-2 gate inputs (streamed)
__device__ float g_h1[(size_t)TSEQ * HID];
__device__ float g_h2[(size_t)TSEQ * HID];
__device__ int   g_flag1[NCHUNK];               // L1 chunk-k h1 complete
__device__ int   g_done [NCHUNK];               // pre2 chunk-k complete (count to NGEMM)

// ---------------- helpers ----------------
__device__ __forceinline__ uint32_t smem_u32(const void* p) {
    return (uint32_t)__cvta_generic_to_shared(p);
}
__device__ __forceinline__ u64 ffma2(u64 a, u64 b, u64 c) {
    u64 d;
    asm("fma.rn.f32x2 %0, %1, %2, %3;" : "=l"(d) : "l"(a), "l"(b), "l"(c));
    return d;
}
__device__ __forceinline__ u64 fadd2(u64 a, u64 b) {
    u64 d;
    asm("add.rn.f32x2 %0, %1, %2;" : "=l"(d) : "l"(a), "l"(b));
    return d;
}
__device__ __forceinline__ float2 unpack2(u64 a) {
    float2 r;
    asm("mov.b64 {%0, %1}, %2;" : "=f"(r.x), "=f"(r.y) : "l"(a));
    return r;
}
__device__ __forceinline__ float fast_sigmoid(float x) {
    return __fdividef(1.f, 1.f + __expf(-x));
}
__device__ __forceinline__ float fast_tanh(float x) {
    return 1.f - __fdividef(2.f, __expf(2.f * x) + 1.f);
}
__device__ __forceinline__ void mbar_wait_cta(uint32_t addr, unsigned parity) {
    asm volatile(
        "{\n\t"
        ".reg .pred P1;\n\t"
        "WAIT_%=:\n\t"
        "mbarrier.try_wait.parity.acquire.cta.shared::cta.b64 P1, [%0], %1, 0x989680;\n\t"
        "@P1 bra DONE_%=;\n\t"
        "bra WAIT_%=;\n\t"
        "DONE_%=:\n\t"
        "}"
        :: "r"(addr), "r"(parity) : "memory");
}
__device__ __forceinline__ void st_release_gpu(int* p, int v) {
    asm volatile("st.release.gpu.global.s32 [%0], %1;" :: "l"(p), "r"(v) : "memory");
}
__device__ __forceinline__ int ld_acquire_gpu(const int* p) {
    int v;
    asm volatile("ld.acquire.gpu.global.s32 %0, [%1];" : "=r"(v) : "l"(p) : "memory");
    return v;
}

// ============================================================================
// Fused pipeline kernel. grid = 36, cluster_dims = 2, 256 thr/CTA.
//   cluster 0 (CTA 0,1): layer-1 LSTM scan (R8 st.async protocol, unchanged)
//   cluster 1 (CTA 2,3): layer-2 LSTM scan, chunk-gated on g_done
//   CTA 4..35: 32 pre2 GEMM workers (8 timesteps per chunk each),
//              chunk-gated on g_flag1
// R9 post-mortem: 4 workers were wavefront-bound (~275us/chunk > 150us scan
// cadence) and rate-limited the whole pipeline. 32 workers -> ~34us/chunk.
// ============================================================================
__global__ void __cluster_dims__(2, 1, 1) __launch_bounds__(256, 1)
fused_lstm_kernel(const float* __restrict__ W_hh1,
                  const float* __restrict__ W_hh2,
                  const float* __restrict__ W_ih2,
                  const float* __restrict__ b_ih2,
                  const float* __restrict__ b_hh2)
{
    __shared__ __align__(16) float lh[4][64];
    __shared__ __align__(16) float rh[4][64];
    __shared__ __align__(8) u64 bar_rem[4];
    __shared__ __align__(16) float As[8 * HID];   // GEMM h1 staging

    const int tid = threadIdx.x;
    const int cid = blockIdx.x >> 1;              // cluster id

    // ========================== GEMM worker path ==========================
    if (cid >= 2) {
        const int w = blockIdx.x - 4;             // 0..NGEMM-1
        const float bias0 = b_ih2[tid] + b_hh2[tid];
        const float bias1 = b_ih2[tid + 256] + b_hh2[tid + 256];
        const float* wr0 = W_ih2 + (size_t)tid * HID;
        const float* wr1 = W_ih2 + (size_t)(tid + 256) * HID;

        for (int k = 0; k < NCHUNK; k++) {
            if (tid == 0) while (ld_acquire_gpu(&g_flag1[k]) == 0) {}
            __syncthreads();

            const int t0 = k * CHUNK + w * (CHUNK / NGEMM);   // 8 timesteps
            for (int idx = tid; idx < 8 * HID; idx += 256)
                As[idx] = g_h1[(size_t)t0 * HID + idx];
            __syncthreads();

            float acc0[8], acc1[8];
#pragma unroll
            for (int i = 0; i < 8; i++) { acc0[i] = bias0; acc1[i] = bias1; }
#pragma unroll 4
            for (int kk = 0; kk < HID; kk++) {
                float w0 = __ldg(wr0 + kk);
                float w1 = __ldg(wr1 + kk);
#pragma unroll
                for (int i = 0; i < 8; i++) {
                    float hvv = As[i * HID + kk];
                    acc0[i] = fmaf(w0, hvv, acc0[i]);
                    acc1[i] = fmaf(w1, hvv, acc1[i]);
                }
            }
#pragma unroll
            for (int i = 0; i < 8; i++) {
                g_pre2[(size_t)(t0 + i) * GROWS + tid]       = acc0[i];
                g_pre2[(size_t)(t0 + i) * GROWS + tid + 256] = acc1[i];
            }
            __syncthreads();
            if (tid == 0) { __threadfence(); atomicAdd(&g_done[k], 1); }
        }
        return;
    }

    // ============================ scan path ================================
    const int layer = cid;                         // 0 or 1
    const float* __restrict__ pre = layer ? g_pre2 : g_pre;
    float* __restrict__ hout = layer ? g_h2 : g_h1;
    const float* __restrict__ W_hh = layer ? W_hh2 : W_hh1;

    const int lane = tid & 31;
    const int warp = tid >> 5;
    unsigned rank;
    asm("mov.u32 %0, %%cluster_ctarank;" : "=r"(rank));
    const unsigned peer = rank ^ 1u;

    const int gate = lane & 3;                 // 0..3 = i,f,g,o
    const int uc   = warp * 8 + (lane >> 2);   // unit within CTA [0,64)
    const int j    = (int)rank * 64 + uc;      // global hidden unit
    const int row  = gate * HID + j;           // gate row [0,512)

    // ---- weights: local half = cols [64*rank, +64), remote half = other 64
    u64 wl[32], wr_[32];
    {
        const ulonglong2* wsl = reinterpret_cast<const ulonglong2*>(
            W_hh + (size_t)row * HID + 64 * rank);
        const ulonglong2* wsr = reinterpret_cast<const ulonglong2*>(
            W_hh + (size_t)row * HID + 64 * peer);
#pragma unroll
        for (int i = 0; i < 16; i++) {
            ulonglong2 a = wsl[i];
            wl[2 * i] = a.x; wl[2 * i + 1] = a.y;
            ulonglong2 b = wsr[i];
            wr_[2 * i] = b.x; wr_[2 * i + 1] = b.y;
        }
    }

    // ---- init ring slot 0 (h_0 = 0) and tx-barriers (count = 1)
    if (tid < 64) {
#pragma unroll
        for (int b = 0; b < 4; b++) { lh[b][tid] = 0.f; rh[b][tid] = 0.f; }
    }
    const uint32_t barb = smem_u32(bar_rem);
    if (tid == 0) {
#pragma unroll
        for (int b = 0; b < 4; b++)
            asm volatile("mbarrier.init.shared.b64 [%0], %1;"
                         :: "r"(barb + (unsigned)(b * 8)), "r"(1u));
        asm volatile("mbarrier.arrive.shared::cta.b64 _, [%0];"
                     :: "r"(barb) : "memory");
#pragma unroll
        for (int b = 1; b < 4; b++)
            asm volatile("mbarrier.arrive.expect_tx.shared.b64 _, [%0], %1;"
                         :: "r"(barb + (unsigned)(b * 8)), "r"(256u) : "memory");
        asm volatile("fence.mbarrier_init.release.cluster;" ::: "memory");
    }
    __syncthreads();
    asm volatile("barrier.cluster.arrive.aligned;" ::: "memory");
    asm volatile("barrier.cluster.wait.aligned;"   ::: "memory");

    uint32_t peer_rh, peer_bar;
    asm("mapa.shared::cluster.u32 %0, %1, %2;"
        : "=r"(peer_rh) : "r"(smem_u32(rh)), "r"(peer));
    asm("mapa.shared::cluster.u32 %0, %1, %2;"
        : "=r"(peer_bar) : "r"(barb), "r"(peer));

    float c = 0.f;                          // cell state (owner lanes, gate 0)

    for (int k = 0; k < NCHUNK; k++) {
        // L2 gates on pre2-chunk completion (acquire); L1 runs free
        if (layer == 1) {
            if (tid == 0) while (ld_acquire_gpu(&g_done[k]) < NGEMM) {}
            __syncthreads();
        }

        const int s0 = k * CHUNK;
        float pcur  = pre[(size_t)s0 * GROWS + row];
        float pnext = pre[(size_t)(s0 + 1) * GROWS + row];

        for (int si = 0; si < CHUNK; si++) {
            const int s = s0 + si;
            float pfut = 0.f;
            if (si + 2 < CHUNK) pfut = pre[(size_t)(s + 2) * GROWS + row];

            const int buf = s & 3;
            const unsigned ph = (unsigned)((s >> 2) & 1);

            // ---- 1. local-half matvec
            u64 a0 = 0ull, a1 = 0ull, a2 = 0ull, a3 = 0ull;
            {
                const ulonglong2* hp = reinterpret_cast<const ulonglong2*>(lh[buf]);
#pragma unroll
                for (int i = 0; i < 16; i += 2) {
                    ulonglong2 x = hp[i];
                    ulonglong2 y = hp[i + 1];
                    a0 = ffma2(wl[2 * i],     x.x, a0);
                    a1 = ffma2(wl[2 * i + 1], x.y, a1);
                    a2 = ffma2(wl[2 * i + 2], y.x, a2);
                    a3 = ffma2(wl[2 * i + 3], y.y, a3);
                }
            }

            // ---- 2. wait peer tx (cta-scope acquire)
            mbar_wait_cta(barb + (unsigned)(buf * 8), ph);

            // ---- 3. re-arm slot for its next fill
            if (tid == 0)
                asm volatile("mbarrier.arrive.expect_tx.shared.b64 _, [%0], %1;"
                             :: "r"(barb + (unsigned)(buf * 8)), "r"(256u) : "memory");

            // ---- 4. remote-half matvec
            {
                const ulonglong2* hp = reinterpret_cast<const ulonglong2*>(rh[buf]);
#pragma unroll
                for (int i = 0; i < 16; i += 2) {
                    ulonglong2 x = hp[i];
                    ulonglong2 y = hp[i + 1];
                    a0 = ffma2(wr_[2 * i],     x.x, a0);
                    a1 = ffma2(wr_[2 * i + 1], x.y, a1);
                    a2 = ffma2(wr_[2 * i + 2], y.x, a2);
                    a3 = ffma2(wr_[2 * i + 3], y.y, a3);
                }
            }
            float2 sm2 = unpack2(fadd2(fadd2(a0, a1), fadd2(a2, a3)));
            float gval = sm2.x + sm2.y + pcur;

            // ---- 5. activation + gather to owner lane
            float av = (gate == 2) ? fast_tanh(gval) : fast_sigmoid(gval);
            const unsigned bl = (unsigned)(lane & ~3);
            float fv = __shfl_sync(0xffffffffu, av, bl + 1);
            float gv = __shfl_sync(0xffffffffu, av, bl + 2);
            float ov = __shfl_sync(0xffffffffu, av, bl + 3);

            // ---- 6. owner epilogue
            const int nbuf = (s + 1) & 3;
            if (gate == 0) {
                c = fv * c + av * gv;
                float hv = ov * fast_tanh(c);

                const unsigned roff = (unsigned)((nbuf * 64 + uc) * 4);
                asm volatile(
                    "st.async.shared::cluster.mbarrier::complete_tx::bytes.b32 "
                    "[%0], %1, [%2];"
                    :: "r"(peer_rh + roff), "r"(__float_as_uint(hv)),
                       "r"(peer_bar + (unsigned)(nbuf * 8)) : "memory");

                lh[nbuf][uc] = hv;
                hout[(size_t)s * HID + j] = hv;
            }

            // ---- 7. publish lh; certify ring reads
            __syncthreads();

            pcur = pnext;
            pnext = pfut;
        }

        // L1 publishes "h1 chunk k complete"
        if (layer == 0) {
            if (tid == 0) { __threadfence(); st_release_gpu(&g_flag1[k], 1); }
        }
    }

    asm volatile("barrier.cluster.arrive.aligned;" ::: "memory");
    asm volatile("barrier.cluster.wait.aligned;"   ::: "memory");
}

// ============================================================================
// pre1 = x @ W_ih1^T + (b_ih1 + b_hh1); block 0 also zeroes the pipe flags.
// ============================================================================
__global__ void __launch_bounds__(512)
pre1_kernel(const float* __restrict__ x, const float* __restrict__ W,
            const float* __restrict__ ba, const float* __restrict__ bb)
{
    constexpr int K = 50, BT = 8;
    __shared__ float Axs[BT * K];

    if (blockIdx.x == 0 && threadIdx.x < NCHUNK) {
        g_flag1[threadIdx.x] = 0;
        g_done[threadIdx.x]  = 0;
    }

    const int t0 = blockIdx.x * BT;
    for (int idx = threadIdx.x; idx < BT * K; idx += 512)
        Axs[idx] = x[(size_t)t0 * K + idx];
    __syncthreads();

    const int r = threadIdx.x;
    float bias = ba[r] + bb[r];
    float acc[BT];
#pragma unroll
    for (int i = 0; i < BT; i++) acc[i] = bias;

    const float* wr = W + (size_t)r * K;
#pragma unroll 2
    for (int k = 0; k < K; k++) {
        float wv = __ldg(wr + k);
#pragma unroll
        for (int i = 0; i < BT; i++) acc[i] = fmaf(wv, Axs[i * K + k], acc[i]);
    }
#pragma unroll
    for (int i = 0; i < BT; i++)
        g_pre[(size_t)(t0 + i) * GROWS + r] = acc[i];
}

// ============================================================================
// Final FC: out[t, o] = fc_b[o] + sum_k g_h2[t,k] * fc_W[o,k]   (OUT = 5)
// ============================================================================
__global__ void __launch_bounds__(256)
fc_kernel(const float* __restrict__ fcW, const float* __restrict__ fcb,
          float* __restrict__ out)
{
    __shared__ float Ws[5 * HID];
    __shared__ float bs[5];
    for (int idx = threadIdx.x; idx < 5 * HID; idx += 256) Ws[idx] = fcW[idx];
    if (threadIdx.x < 5) bs[threadIdx.x] = fcb[threadIdx.x];
    __syncthreads();

    const int t = blockIdx.x * 256 + threadIdx.x;
    float acc[5];
#pragma unroll
    for (int o = 0; o < 5; o++) acc[o] = bs[o];

    const float4* hp = reinterpret_cast<const float4*>(&g_h2[(size_t)t * HID]);
#pragma unroll 4
    for (int k4 = 0; k4 < HID / 4; k4++) {
        float4 h = hp[k4];
#pragma unroll
        for (int o = 0; o < 5; o++) {
            acc[o] = fmaf(h.x, Ws[o * HID + 4 * k4 + 0], acc[o]);
            acc[o] = fmaf(h.y, Ws[o * HID + 4 * k4 + 1], acc[o]);
            acc[o] = fmaf(h.z, Ws[o * HID + 4 * k4 + 2], acc[o]);
            acc[o] = fmaf(h.w, Ws[o * HID + 4 * k4 + 3], acc[o]);
        }
    }
#pragma unroll
    for (int o = 0; o < 5; o++) out[(size_t)t * 5 + o] = acc[o];
}

// ============================================================================
// kernel_launch: pre1 (+flag reset) -> fused pipeline (L1 | GEMMx32 | L2) -> FC
// ============================================================================
extern "C" void kernel_launch(void* const* d_in, const int* in_sizes, int n_in,
                              void* d_out, int out_size)
{
    (void)in_sizes; (void)n_in; (void)out_size;

    const float* x     = (const float*)d_in[0];
    const float* W_ih1 = (const float*)d_in[1];
    const float* W_hh1 = (const float*)d_in[2];
    const float* b_ih1 = (const float*)d_in[3];
    const float* b_hh1 = (const float*)d_in[4];
    const float* W_ih2 = (const float*)d_in[5];
    const float* W_hh2 = (const float*)d_in[6];
    const float* b_ih2 = (const float*)d_in[7];
    const float* b_hh2 = (const float*)d_in[8];
    const float* fc_W  = (const float*)d_in[9];
    const float* fc_b  = (const float*)d_in[10];
    float* out = (float*)d_out;

    pre1_kernel<<<TSEQ / 8, 512>>>(x, W_ih1, b_ih1, b_hh1);
    fused_lstm_kernel<<<4 + NGEMM, 256>>>(W_hh1, W_hh2, W_ih2, b_ih2, b_hh2);
    fc_kernel<<<TSEQ / 256, 256>>>(fc_W, fc_b, out);
}